// round 3
// baseline (speedup 1.0000x reference)
#include <cuda_runtime.h>
#include <cstdint>

#define NB 2
#define LL 256
#define HH 8
#define DD 64
#define EE 512
#define INVS 0.70710678118654752440f

typedef unsigned long long ull;

__device__ __forceinline__ ull fma2(ull a, ull b, ull c) {
    ull d;
    asm("fma.rn.f32x2 %0, %1, %2, %3;" : "=l"(d) : "l"(a), "l"(b), "l"(c));
    return d;
}
__device__ __forceinline__ ull add2(ull a, ull b) {
    ull d;
    asm("add.rn.f32x2 %0, %1, %2;" : "=l"(d) : "l"(a), "l"(b));
    return d;
}
__device__ __forceinline__ ull pack2(float x, float y) {
    ull d;
    asm("mov.b64 %0, {%1, %2};" : "=l"(d) : "r"(__float_as_uint(x)), "r"(__float_as_uint(y)));
    return d;
}
__device__ __forceinline__ float lohi(ull s) {
    unsigned lo, hi;
    asm("mov.b64 {%0, %1}, %2;" : "=r"(lo), "=r"(hi) : "l"(s));
    return __uint_as_float(lo) + __uint_as_float(hi);
}
__device__ __forceinline__ void unpk(ull s, float& a, float& b) {
    unsigned lo, hi;
    asm("mov.b64 {%0, %1}, %2;" : "=r"(lo), "=r"(hi) : "l"(s));
    a = __uint_as_float(lo);
    b = __uint_as_float(hi);
}

// ---- scratch ----
__device__ float g_W[5 * 64 * 64];        // Mqk, Mp, Wa, Wb, WvT (layout [w][m][i], i contiguous)
__device__ float g_qm[NB * LL * EE];
__device__ float g_pm[NB * LL * EE];
__device__ float g_a [NB * LL * EE];
__device__ float g_b [NB * LL * EE];
__device__ float g_vp[NB * LL * EE];
__device__ float g_base[NB * HH * LL * LL];
__device__ float g_outh[NB * LL * EE];

// ---- kA0: combined 64x64 weights ----
__global__ void kA0(const float* __restrict__ Wq, const float* __restrict__ Wk,
                    const float* __restrict__ Wpq, const float* __restrict__ Wpk,
                    const float* __restrict__ Wrk, const float* __restrict__ Wrq,
                    const float* __restrict__ Wv) {
    int w = blockIdx.x;
    int tid = threadIdx.x;
    __shared__ float Wr[4096];
    if (w == 4) {
        for (int o = tid; o < 4096; o += 256) {
            int m = o >> 6, i = o & 63;
            g_W[4 * 4096 + o] = Wv[i * 64 + m];   // [m][i] with value Wv[i][m]
        }
        return;
    }
    const float *Wl, *Wrg;
    if (w == 0)      { Wl = Wq;  Wrg = Wk;  }
    else if (w == 1) { Wl = Wpq; Wrg = Wpk; }
    else if (w == 2) { Wl = Wq;  Wrg = Wrk; }
    else             { Wl = Wk;  Wrg = Wrq; }
    for (int o = tid; o < 4096; o += 256) Wr[o] = Wrg[o];
    __syncthreads();
    int m = tid & 63, jg = tid >> 6;
    float acc[16];
#pragma unroll
    for (int j = 0; j < 16; j++) acc[j] = 0.f;
    for (int t = 0; t < 64; t++) {
        float xl = Wl[t * 64 + m];
#pragma unroll
        for (int j = 0; j < 16; j++) acc[j] = fmaf(xl, Wr[t * 64 + jg * 16 + j], acc[j]);
    }
#pragma unroll
    for (int j = 0; j < 16; j++) g_W[w * 4096 + m * 64 + jg * 16 + j] = acc[j];
}

// ---- kA: 5 fused per-head projections; 256 threads, 2 output cols each (f32x2) ----
// qm, pm scaled by INVS (folds 1/sqrt2 into base); a, b scaled by INVS.
__global__ void kA(const float* __restrict__ values, const float* __restrict__ keys,
                   const float* __restrict__ query, const float* __restrict__ pos) {
    __shared__ float xq[512], xk[512], xp[512], xv[512];
    int row = blockIdx.x;
    int t = threadIdx.x;
    xq[t] = query [row * 512 + t];  xq[t + 256] = query [row * 512 + 256 + t];
    xk[t] = keys  [row * 512 + t];  xk[t + 256] = keys  [row * 512 + 256 + t];
    xp[t] = pos   [row * 512 + t];  xp[t + 256] = pos   [row * 512 + 256 + t];
    xv[t] = values[row * 512 + t];  xv[t + 256] = values[row * 512 + 256 + t];
    __syncthreads();
    int i0 = 2 * t;
    int hb = i0 & ~63;              // head base (warp-uniform)
    int il = i0 & 63;
    const float* Mqk = g_W;
    const float* Mp  = g_W + 4096;
    const float* Wa  = g_W + 8192;
    const float* Wb  = g_W + 12288;
    const float* WvT = g_W + 16384;
    ull aqm = 0, apm = 0, aa = 0, ab = 0, av = 0;
#pragma unroll 8
    for (int m = 0; m < 64; m++) {
        float q_ = xq[hb + m], k_ = xk[hb + m], p_ = xp[hb + m], v_ = xv[hb + m];
        ull q2 = pack2(q_, q_), k2 = pack2(k_, k_), p2 = pack2(p_, p_), v2 = pack2(v_, v_);
        int wi = m * 64 + il;
        aqm = fma2(q2, *(const ull*)&Mqk[wi], aqm);
        apm = fma2(p2, *(const ull*)&Mp [wi], apm);
        aa  = fma2(q2, *(const ull*)&Wa [wi], aa);
        ab  = fma2(k2, *(const ull*)&Wb [wi], ab);
        av  = fma2(v2, *(const ull*)&WvT[wi], av);
    }
    size_t o = (size_t)row * 512 + i0;
    ull s2 = pack2(INVS, INVS);
    ull z = 0;
    *(ull*)&g_qm[o] = fma2(aqm, s2, z);
    *(ull*)&g_pm[o] = fma2(apm, s2, z);
    *(ull*)&g_a [o] = fma2(aa,  s2, z);
    *(ull*)&g_b [o] = fma2(ab,  s2, z);
    *(ull*)&g_vp[o] = av;
}

// ---- kB: base[n,h,q,k] = qm.keys + pm.pos (+ mask term); f32x2 packed across k ----
__global__ void kB(const float* __restrict__ keys, const float* __restrict__ pos,
                   const float* __restrict__ mask) {
    __shared__ float Ush[2][32][64];
    __shared__ float Vsh[2][64][72];    // [src][c][k], pad 72 for 16B-aligned rows
    int qt = blockIdx.x >> 2, kt = blockIdx.x & 3;
    int h = blockIdx.y, n = blockIdx.z;
    int tid = threadIdx.x;
    int kid = tid & 15, qid = tid >> 4;
#pragma unroll
    for (int ii = 0; ii < 16; ii++) {
        int flat = ii * 256 + tid;
        int src = flat >> 11, q = (flat >> 6) & 31, c = flat & 63;
        Ush[src][q][c] = (src ? g_pm : g_qm)[((size_t)(n * 256 + qt * 32 + q)) * 512 + h * 64 + c];
    }
#pragma unroll
    for (int ii = 0; ii < 32; ii++) {
        int flat = ii * 256 + tid;
        int src = flat >> 12, k = (flat >> 6) & 63, c = flat & 63;
        const float* V = src ? pos : keys;
        Vsh[src][c][k] = V[((size_t)(n * 256 + kt * 64 + k)) * 512 + h * 64 + c];
    }
    __syncthreads();
    ull acc2[2][2];
    acc2[0][0] = acc2[0][1] = acc2[1][0] = acc2[1][1] = 0ull;
#pragma unroll
    for (int src = 0; src < 2; src++) {
#pragma unroll 4
        for (int c = 0; c < 64; c++) {
            float u0 = Ush[src][qid][c], u1 = Ush[src][qid + 16][c];
            ull u02 = pack2(u0, u0), u12 = pack2(u1, u1);
            ulonglong2 v2 = *(const ulonglong2*)&Vsh[src][c][kid * 4];
            acc2[0][0] = fma2(u02, v2.x, acc2[0][0]);
            acc2[0][1] = fma2(u02, v2.y, acc2[0][1]);
            acc2[1][0] = fma2(u12, v2.x, acc2[1][0]);
            acc2[1][1] = fma2(u12, v2.y, acc2[1][1]);
        }
    }
    float4 m4 = *(const float4*)(mask + n * 256 + kt * 64 + kid * 4);
    float nm0 = (1.0f - m4.x) * -1e9f, nm1 = (1.0f - m4.y) * -1e9f;
    float nm2 = (1.0f - m4.z) * -1e9f, nm3 = (1.0f - m4.w) * -1e9f;
#pragma unroll
    for (int a = 0; a < 2; a++) {
        int q = qt * 32 + qid + 16 * a;
        float4 r;
        unpk(acc2[a][0], r.x, r.y);
        unpk(acc2[a][1], r.z, r.w);
        r.x += nm0; r.y += nm1; r.z += nm2; r.w += nm3;
        *(float4*)&g_base[((size_t)((n * 8 + h) * 256 + q)) * 256 + kt * 64 + kid * 4] = r;
    }
}

// ---- kC: rel stream (direct LDG.128) + softmax + fused attn@v ----
__global__ void __launch_bounds__(128, 5)
kC(const float* __restrict__ rel) {
    __shared__ float eng[2][4][256];
    const int n = blockIdx.z, hh = blockIdx.y, qp = blockIdx.x;
    const int q0 = qp * 2;
    const int tid = threadIdx.x;
    const int w = tid >> 5, l = tid & 31;
    const int h = hh * 4 + w;
    const int kk = l & 7, ds = l >> 3;

    // init eng from base (already scaled + masked)
#pragma unroll
    for (int ii = 0; ii < 16; ii++) {
        int flat = ii * 128 + tid;
        int qi = flat >> 10, h2 = (flat >> 8) & 3, k = flat & 255;
        eng[qi][h2][k] = g_base[((size_t)((n * 8 + hh * 4 + h2) * 256 + q0 + qi)) * 256 + k];
    }
    // preload a (scaled by 1/sqrt2)
    ull av[2][8];
#pragma unroll
    for (int q = 0; q < 2; q++) {
        const ulonglong2* ap =
            (const ulonglong2*)(g_a + ((size_t)(n * 256 + q0 + q)) * 512 + h * 64 + ds * 16);
#pragma unroll
        for (int u = 0; u < 4; u++) {
            ulonglong2 t2 = ap[u];
            av[q][2 * u] = t2.x; av[q][2 * u + 1] = t2.y;
        }
    }
    __syncthreads();

    const float* relb = rel + (((size_t)(n * 256 + q0)) * 256) * 512 + h * 64 + ds * 16;
#pragma unroll 2
    for (int t = 0; t < 32; t++) {
        int k = t * 8 + kk;
        const ulonglong2* bp =
            (const ulonglong2*)(g_b + ((size_t)(n * 256 + k)) * 512 + h * 64 + ds * 16);
        const ulonglong2* r0 = (const ulonglong2*)(relb + (size_t)k * 512);
        const ulonglong2* r1 = (const ulonglong2*)(relb + (size_t)k * 512 + 256 * 512);
        ull s0 = 0, s1 = 0;
#pragma unroll
        for (int u = 0; u < 4; u++) {
            ulonglong2 bb = bp[u];
            ulonglong2 ra = r0[u];
            ulonglong2 rb = r1[u];
            s0 = fma2(ra.x, add2(av[0][2 * u],     bb.x), s0);
            s0 = fma2(ra.y, add2(av[0][2 * u + 1], bb.y), s0);
            s1 = fma2(rb.x, add2(av[1][2 * u],     bb.x), s1);
            s1 = fma2(rb.y, add2(av[1][2 * u + 1], bb.y), s1);
        }
        float f0 = lohi(s0), f1 = lohi(s1);
        f0 += __shfl_xor_sync(0xffffffffu, f0, 8);
        f0 += __shfl_xor_sync(0xffffffffu, f0, 16);
        f1 += __shfl_xor_sync(0xffffffffu, f1, 8);
        f1 += __shfl_xor_sync(0xffffffffu, f1, 16);
        if (ds == 0) {
            eng[0][w][k] += f0;
            eng[1][w][k] += f1;
        }
    }
    __syncwarp();

    // softmax per warp (head h), q0 and q0+1; write probs back into eng
#pragma unroll
    for (int qi = 0; qi < 2; qi++) {
        float v[8];
        float m = -1e30f;
#pragma unroll
        for (int j = 0; j < 8; j++) {
            v[j] = eng[qi][w][l + 32 * j];
            m = fmaxf(m, v[j]);
        }
#pragma unroll
        for (int off = 16; off; off >>= 1)
            m = fmaxf(m, __shfl_xor_sync(0xffffffffu, m, off));
        float s = 0.f;
#pragma unroll
        for (int j = 0; j < 8; j++) {
            v[j] = __expf(v[j] - m);
            s += v[j];
        }
#pragma unroll
        for (int off = 16; off; off >>= 1)
            s += __shfl_xor_sync(0xffffffffu, s, off);
        float inv = 1.0f / s;
#pragma unroll
        for (int j = 0; j < 8; j++)
            eng[qi][w][l + 32 * j] = v[j] * inv;
    }
    __syncwarp();

    // fused attn @ v : lane -> d pair (2l, 2l+1), f32x2 packed across d
    ull acc0 = 0, acc1 = 0;
    const float* vpb = g_vp + ((size_t)(n * 256)) * 512 + h * 64 + 2 * l;
#pragma unroll 8
    for (int k = 0; k < 256; k++) {
        ull v2 = *(const ull*)(vpb + (size_t)k * 512);
        float a0 = eng[0][w][k], a1 = eng[1][w][k];
        acc0 = fma2(pack2(a0, a0), v2, acc0);
        acc1 = fma2(pack2(a1, a1), v2, acc1);
    }
    *(ull*)(g_outh + ((size_t)(n * 256 + q0))     * 512 + h * 64 + 2 * l) = acc0;
    *(ull*)(g_outh + ((size_t)(n * 256 + q0 + 1)) * 512 + h * 64 + 2 * l) = acc1;
}

// ---- kE: out = outh @ Wout^T + bout (f32x2 packed across j) ----
__global__ void kE(const float* __restrict__ Wout, const float* __restrict__ bout,
                   float* __restrict__ out) {
    __shared__ float Xs[16][64];
    __shared__ float Ws[64][72];
    int rt = blockIdx.x, jt = blockIdx.y;
    int tid = threadIdx.x;
    int jid = tid & 15, rid = tid >> 4;
    ull acc2[2];
    acc2[0] = acc2[1] = 0ull;
    for (int mt = 0; mt < 8; mt++) {
        __syncthreads();
#pragma unroll
        for (int ii = 0; ii < 4; ii++) {
            int flat = ii * 256 + tid;
            int r = flat >> 6, c = flat & 63;
            Xs[r][c] = g_outh[(size_t)(rt * 16 + r) * 512 + mt * 64 + c];
        }
#pragma unroll
        for (int ii = 0; ii < 16; ii++) {
            int flat = ii * 256 + tid;
            int j = flat >> 6, ml = flat & 63;
            Ws[ml][j] = Wout[(size_t)(jt * 64 + j) * 512 + mt * 64 + ml];
        }
        __syncthreads();
#pragma unroll 8
        for (int ml = 0; ml < 64; ml++) {
            float u = Xs[rid][ml];
            ull u2 = pack2(u, u);
            ulonglong2 w2 = *(const ulonglong2*)&Ws[ml][jid * 4];
            acc2[0] = fma2(u2, w2.x, acc2[0]);
            acc2[1] = fma2(u2, w2.y, acc2[1]);
        }
    }
    int row = rt * 16 + rid;
    int col = jt * 64 + jid * 4;
    ull b01 = *(const ull*)(bout + col);
    ull b23 = *(const ull*)(bout + col + 2);
    ulonglong2 r;
    r.x = add2(acc2[0], b01);
    r.y = add2(acc2[1], b23);
    *(ulonglong2*)(out + (size_t)row * 512 + col) = r;
}

extern "C" void kernel_launch(void* const* d_in, const int* in_sizes, int n_in,
                              void* d_out, int out_size) {
    const float* values = (const float*)d_in[0];
    const float* keys   = (const float*)d_in[1];
    const float* query  = (const float*)d_in[2];
    const float* pos    = (const float*)d_in[3];
    const float* rel    = (const float*)d_in[4];
    const float* mask   = (const float*)d_in[5];
    const float* Wv   = (const float*)d_in[6];
    const float* Wk   = (const float*)d_in[7];
    const float* Wq   = (const float*)d_in[8];
    const float* Wpq  = (const float*)d_in[9];
    const float* Wpk  = (const float*)d_in[10];
    const float* Wrk  = (const float*)d_in[11];
    const float* Wrq  = (const float*)d_in[12];
    const float* Wout = (const float*)d_in[13];
    const float* bout = (const float*)d_in[14];
    float* out = (float*)d_out;

    kA0<<<5, 256>>>(Wq, Wk, Wpq, Wpk, Wrk, Wrq, Wv);
    kA<<<NB * LL, 256>>>(values, keys, query, pos);
    kB<<<dim3(32, HH, NB), 256>>>(keys, pos, mask);
    kC<<<dim3(LL / 2, 2, NB), 128>>>(rel);
    kE<<<dim3(32, 8), 256>>>(Wout, bout, out);
}

// round 4
// speedup vs baseline: 1.0940x; 1.0940x over previous
#include <cuda_runtime.h>
#include <cstdint>

#define NB 2
#define LL 256
#define HH 8
#define DD 64
#define EE 512
#define INVS 0.70710678118654752440f

typedef unsigned long long ull;

__device__ __forceinline__ ull fma2(ull a, ull b, ull c) {
    ull d;
    asm("fma.rn.f32x2 %0, %1, %2, %3;" : "=l"(d) : "l"(a), "l"(b), "l"(c));
    return d;
}
__device__ __forceinline__ ull add2(ull a, ull b) {
    ull d;
    asm("add.rn.f32x2 %0, %1, %2;" : "=l"(d) : "l"(a), "l"(b));
    return d;
}
__device__ __forceinline__ ull pack2(float x, float y) {
    ull d;
    asm("mov.b64 %0, {%1, %2};" : "=l"(d) : "r"(__float_as_uint(x)), "r"(__float_as_uint(y)));
    return d;
}
__device__ __forceinline__ float lohi(ull s) {
    unsigned lo, hi;
    asm("mov.b64 {%0, %1}, %2;" : "=r"(lo), "=r"(hi) : "l"(s));
    return __uint_as_float(lo) + __uint_as_float(hi);
}
__device__ __forceinline__ void unpk(ull s, float& a, float& b) {
    unsigned lo, hi;
    asm("mov.b64 {%0, %1}, %2;" : "=r"(lo), "=r"(hi) : "l"(s));
    a = __uint_as_float(lo);
    b = __uint_as_float(hi);
}
__device__ __forceinline__ void cp16(uint32_t dst, const float* src) {
    asm volatile("cp.async.cg.shared.global [%0], [%1], 16;" :: "r"(dst), "l"(src));
}

// ---- scratch ----
__device__ float g_W[5 * 64 * 64];        // Mqk, Mp, Wa, Wb, WvT : [w][m][i]
__device__ float g_qm[NB * LL * EE];
__device__ float g_pm[NB * LL * EE];
__device__ float g_a [NB * LL * EE];      // PERMUTED rows
__device__ float g_b [NB * LL * EE];      // PERMUTED rows
__device__ float g_vp[NB * LL * EE];
__device__ float g_base[NB * HH * LL * LL];
__device__ float g_attn[NB * HH * LL * LL];
__device__ float g_outh[NB * LL * EE];

// ---- kA0: combined 64x64 weights ----
__global__ void kA0(const float* __restrict__ Wq, const float* __restrict__ Wk,
                    const float* __restrict__ Wpq, const float* __restrict__ Wpk,
                    const float* __restrict__ Wrk, const float* __restrict__ Wrq,
                    const float* __restrict__ Wv) {
    int w = blockIdx.x;
    int tid = threadIdx.x;
    __shared__ float Wr[4096];
    if (w == 4) {
        for (int o = tid; o < 4096; o += 256) {
            int m = o >> 6, i = o & 63;
            g_W[4 * 4096 + o] = Wv[i * 64 + m];
        }
        return;
    }
    const float *Wl, *Wrg;
    if (w == 0)      { Wl = Wq;  Wrg = Wk;  }
    else if (w == 1) { Wl = Wpq; Wrg = Wpk; }
    else if (w == 2) { Wl = Wq;  Wrg = Wrk; }
    else             { Wl = Wk;  Wrg = Wrq; }
    for (int o = tid; o < 4096; o += 256) Wr[o] = Wrg[o];
    __syncthreads();
    int m = tid & 63, jg = tid >> 6;
    float acc[16];
#pragma unroll
    for (int j = 0; j < 16; j++) acc[j] = 0.f;
    for (int t = 0; t < 64; t++) {
        float xl = Wl[t * 64 + m];
#pragma unroll
        for (int j = 0; j < 16; j++) acc[j] = fmaf(xl, Wr[t * 64 + jg * 16 + j], acc[j]);
    }
#pragma unroll
    for (int j = 0; j < 16; j++) g_W[w * 4096 + m * 64 + jg * 16 + j] = acc[j];
}

// ---- kA: 5 fused projections, 4 rows per block; a/b written PERMUTED ----
__global__ void kA(const float* __restrict__ values, const float* __restrict__ keys,
                   const float* __restrict__ query, const float* __restrict__ pos) {
    __shared__ float xs[4][4][512];   // [tensor][row][col]
    int r0 = blockIdx.x * 4;
    int tid = threadIdx.x;
    const float* srcs[4] = {values, keys, query, pos};
#pragma unroll
    for (int ii = 0; ii < 8; ii++) {
        int flat = ii * 256 + tid;               // float4 index
        int ten = flat >> 9, row = (flat >> 7) & 3, c4 = flat & 127;
        *(float4*)&xs[ten][row][c4 * 4] =
            *(const float4*)(srcs[ten] + (size_t)(r0 + row) * 512 + c4 * 4);
    }
    __syncthreads();
    int i0 = 2 * tid;
    int hb = i0 & ~63, il = i0 & 63;
    const float* Mqk = g_W;
    const float* Mp  = g_W + 4096;
    const float* Wa  = g_W + 8192;
    const float* Wb  = g_W + 12288;
    const float* WvT = g_W + 16384;
    ull aqm[4], apm[4], aa[4], ab[4], av[4];
#pragma unroll
    for (int r = 0; r < 4; r++) { aqm[r]=0; apm[r]=0; aa[r]=0; ab[r]=0; av[r]=0; }
#pragma unroll 4
    for (int m = 0; m < 64; m++) {
        int wi = m * 64 + il;
        ull wqk = *(const ull*)&Mqk[wi];
        ull wp  = *(const ull*)&Mp [wi];
        ull wa  = *(const ull*)&Wa [wi];
        ull wb  = *(const ull*)&Wb [wi];
        ull wv  = *(const ull*)&WvT[wi];
#pragma unroll
        for (int r = 0; r < 4; r++) {
            float v_ = xs[0][r][hb + m], k_ = xs[1][r][hb + m];
            float q_ = xs[2][r][hb + m], p_ = xs[3][r][hb + m];
            aqm[r] = fma2(pack2(q_, q_), wqk, aqm[r]);
            apm[r] = fma2(pack2(p_, p_), wp,  apm[r]);
            aa [r] = fma2(pack2(q_, q_), wa,  aa [r]);
            ab [r] = fma2(pack2(k_, k_), wb,  ab [r]);
            av [r] = fma2(pack2(v_, v_), wv,  av [r]);
        }
    }
    ull s2 = pack2(INVS, INVS);
    ull z = 0;
    int j = i0 >> 2;
    int pi = (((j & 3) << 5) + (j >> 2)) * 4 + (i0 & 3);   // permuted index
#pragma unroll
    for (int r = 0; r < 4; r++) {
        size_t o  = (size_t)(r0 + r) * 512 + i0;
        size_t op = (size_t)(r0 + r) * 512 + pi;
        *(ull*)&g_qm[o]  = fma2(aqm[r], s2, z);
        *(ull*)&g_pm[o]  = fma2(apm[r], s2, z);
        *(ull*)&g_a [op] = fma2(aa [r], s2, z);
        *(ull*)&g_b [op] = fma2(ab [r], s2, z);
        *(ull*)&g_vp[o]  = av[r];
    }
}

// ---- kB: base[n,h,q,k] = qm.keys + pm.pos + mask; swizzled Vsh ----
__global__ void kB(const float* __restrict__ keys, const float* __restrict__ pos,
                   const float* __restrict__ mask) {
    __shared__ float Ush[2][32][64];
    __shared__ float Vsh[2][64][64];   // swizzled: (c,k) -> [c][((k>>2)^(c&15))*4 + (k&3)]
    int qt = blockIdx.x >> 2, kt = blockIdx.x & 3;
    int h = blockIdx.y, n = blockIdx.z;
    int tid = threadIdx.x;
    int kid = tid & 15, qid = tid >> 4;
#pragma unroll
    for (int ii = 0; ii < 4; ii++) {
        int flat = ii * 256 + tid;               // float4 idx
        int src = flat >> 9, q = (flat >> 4) & 31, c4 = flat & 15;
        *(float4*)&Ush[src][q][c4 * 4] =
            *(const float4*)((src ? g_pm : g_qm) +
                             (size_t)(n * 256 + qt * 32 + q) * 512 + h * 64 + c4 * 4);
    }
#pragma unroll
    for (int ii = 0; ii < 8; ii++) {
        int flat = ii * 256 + tid;               // float4 idx
        int src = flat >> 10, k = (flat >> 4) & 63, c4 = flat & 15;
        const float* V = src ? pos : keys;
        float4 v = *(const float4*)(V + (size_t)(n * 256 + kt * 64 + k) * 512 + h * 64 + c4 * 4);
        float vv[4] = {v.x, v.y, v.z, v.w};
#pragma unroll
        for (int i = 0; i < 4; i++) {
            int c = c4 * 4 + i;
            Vsh[src][c][(((k >> 2) ^ (c & 15)) << 2) + (k & 3)] = vv[i];
        }
    }
    __syncthreads();
    ull acc2[2][2];
    acc2[0][0] = acc2[0][1] = acc2[1][0] = acc2[1][1] = 0ull;
#pragma unroll
    for (int src = 0; src < 2; src++) {
#pragma unroll 4
        for (int c = 0; c < 64; c++) {
            float u0 = Ush[src][qid][c], u1 = Ush[src][qid + 16][c];
            ull u02 = pack2(u0, u0), u12 = pack2(u1, u1);
            ulonglong2 v2 = *(const ulonglong2*)&Vsh[src][c][(kid ^ (c & 15)) << 2];
            acc2[0][0] = fma2(u02, v2.x, acc2[0][0]);
            acc2[0][1] = fma2(u02, v2.y, acc2[0][1]);
            acc2[1][0] = fma2(u12, v2.x, acc2[1][0]);
            acc2[1][1] = fma2(u12, v2.y, acc2[1][1]);
        }
    }
    float4 m4 = *(const float4*)(mask + n * 256 + kt * 64 + kid * 4);
    float nm0 = (1.0f - m4.x) * -1e9f, nm1 = (1.0f - m4.y) * -1e9f;
    float nm2 = (1.0f - m4.z) * -1e9f, nm3 = (1.0f - m4.w) * -1e9f;
#pragma unroll
    for (int a = 0; a < 2; a++) {
        int q = qt * 32 + qid + 16 * a;
        float4 r;
        unpk(acc2[a][0], r.x, r.y);
        unpk(acc2[a][1], r.z, r.w);
        r.x += nm0; r.y += nm1; r.z += nm2; r.w += nm3;
        *(float4*)&g_base[((size_t)((n * 8 + h) * 256 + q)) * 256 + kt * 64 + kid * 4] = r;
    }
}

// ---- kC: rel streamed via cp.async (permuted tiles) + softmax ----
// dyn smem: relS[2][16][512] (65536B) + eng[2*8*260] (16640B) = 82176B
__global__ void __launch_bounds__(256, 2)
kC(const float* __restrict__ rel) {
    extern __shared__ float sm[];
    float* relS = sm;                 // [buf*16 + row][512], permuted chunks
    float* eng  = sm + 16384;         // [(q*8+h)*260 + k]
    const int n = blockIdx.y;
    const int q0 = blockIdx.x * 2;
    const int tid = threadIdx.x;
    const int w = tid >> 5, l = tid & 31;
    const int hl = l >> 2;            // head this lane reduces into

    // eng init from base (scaled + masked already)
#pragma unroll
    for (int ii = 0; ii < 4; ii++) {
        int flat = ii * 256 + tid;               // float4 idx over 4096 floats
        int qi = flat >> 9, h = (flat >> 6) & 7, k4 = flat & 63;
        float4 v = *(const float4*)(g_base +
            ((size_t)((n * 8 + h) * 256 + q0 + qi)) * 256 + k4 * 4);
        *(float4*)&eng[(qi * 8 + h) * 260 + k4 * 4] = v;
    }

    // a regs (permuted layout): lane l chunk u -> floats 16l+4u..+4
    ull areg[2][8];
#pragma unroll
    for (int q = 0; q < 2; q++) {
        const ulonglong2* ap = (const ulonglong2*)(g_a + (size_t)(n * 256 + q0 + q) * 512);
#pragma unroll
        for (int u = 0; u < 4; u++) {
            ulonglong2 t2 = ap[u * 32 + l];
            areg[q][2 * u] = t2.x; areg[q][2 * u + 1] = t2.y;
        }
    }

    uint32_t sbase = (uint32_t)__cvta_generic_to_shared(relS);
    const size_t relrow0 = ((size_t)(n * 256 + q0)) * 256;   // row units

    // stage tile 0 (k rows 0..7, q rows 0..1) into buf 0
#pragma unroll
    for (int it = 0; it < 8; it++) {
        int g = it * 256 + tid;                  // chunk index in tile (2048)
        int row = g >> 7, j = g & 127;
        int q = row >> 3, kk = row & 7;
        int p = ((j & 3) << 5) + (j >> 2);
        cp16(sbase + (uint32_t)((row * 512 + p * 4) * 4),
             rel + (relrow0 + (size_t)q * 256 + kk) * 512 + j * 4);
    }
    asm volatile("cp.async.commit_group;");

    for (int t = 0; t < 32; t++) {
        if (t + 1 < 32) {
            int buf2 = (t + 1) & 1;
#pragma unroll
            for (int it = 0; it < 8; it++) {
                int g = it * 256 + tid;
                int row = g >> 7, j = g & 127;
                int q = row >> 3, kk = row & 7;
                int p = ((j & 3) << 5) + (j >> 2);
                cp16(sbase + (uint32_t)(((buf2 * 16 + row) * 512 + p * 4) * 4),
                     rel + (relrow0 + (size_t)q * 256 + (t + 1) * 8 + kk) * 512 + j * 4);
            }
            asm volatile("cp.async.commit_group;");
            asm volatile("cp.async.wait_group 1;");
        } else {
            asm volatile("cp.async.wait_group 0;");
        }
        __syncthreads();

        int buf = t & 1;
        int k = t * 8 + w;
        const ulonglong2* bp = (const ulonglong2*)(g_b + (size_t)(n * 256 + k) * 512);
        ulonglong2 bu[4];
#pragma unroll
        for (int u = 0; u < 4; u++) bu[u] = bp[u * 32 + l];
#pragma unroll
        for (int q = 0; q < 2; q++) {
            const float* rrow = relS + (buf * 16 + q * 8 + w) * 512;
            ull s = 0;
#pragma unroll
            for (int u = 0; u < 4; u++) {
                ulonglong2 ru = *(const ulonglong2*)&rrow[(u * 32 + l) * 4];
                s = fma2(ru.x, add2(areg[q][2 * u],     bu[u].x), s);
                s = fma2(ru.y, add2(areg[q][2 * u + 1], bu[u].y), s);
            }
            float f = lohi(s);
            f += __shfl_xor_sync(0xffffffffu, f, 1);
            f += __shfl_xor_sync(0xffffffffu, f, 2);
            if ((l & 3) == 0) eng[(q * 8 + hl) * 260 + k] += f;
        }
        __syncthreads();
    }

    // softmax: warp w = head w, q0 and q0+1
#pragma unroll
    for (int qi = 0; qi < 2; qi++) {
        float v[8];
        float m = -1e30f;
#pragma unroll
        for (int j = 0; j < 8; j++) {
            v[j] = eng[(qi * 8 + w) * 260 + l + 32 * j];
            m = fmaxf(m, v[j]);
        }
#pragma unroll
        for (int off = 16; off; off >>= 1)
            m = fmaxf(m, __shfl_xor_sync(0xffffffffu, m, off));
        float s = 0.f;
#pragma unroll
        for (int j = 0; j < 8; j++) {
            v[j] = __expf(v[j] - m);
            s += v[j];
        }
#pragma unroll
        for (int off = 16; off; off >>= 1)
            s += __shfl_xor_sync(0xffffffffu, s, off);
        float inv = 1.0f / s;
#pragma unroll
        for (int j = 0; j < 8; j++)
            g_attn[((size_t)((n * 8 + w) * 256 + q0 + qi)) * 256 + l + 32 * j] = v[j] * inv;
    }
}

// ---- kD: outh[n,q,h,d] = sum_k attn[n,h,q,k] * vp[n,k,h,d] ----
__global__ void kD() {
    __shared__ float vsh[64][64];
    __shared__ float ash[32][64];
    int qt = blockIdx.x, h = blockIdx.y, n = blockIdx.z;
    int tid = threadIdx.x;
    int l = tid & 31, qw = tid >> 5;  // 16 warps -> 2 q each
    float acc[2][2];
    acc[0][0] = acc[0][1] = acc[1][0] = acc[1][1] = 0.f;
    for (int kp = 0; kp < 4; kp++) {
        __syncthreads();
#pragma unroll
        for (int ii = 0; ii < 2; ii++) {
            int flat = ii * 512 + tid;           // float4 idx
            int k = flat >> 4, d4 = flat & 15;
            *(float4*)&vsh[k][d4 * 4] = *(const float4*)(g_vp +
                ((size_t)(n * 256 + kp * 64 + k)) * 512 + h * 64 + d4 * 4);
        }
        {
            int q = tid >> 4, k4 = tid & 15;
            *(float4*)&ash[q][k4 * 4] = *(const float4*)(g_attn +
                ((size_t)((n * 8 + h) * 256 + qt * 32 + q)) * 256 + kp * 64 + k4 * 4);
        }
        __syncthreads();
#pragma unroll 4
        for (int kk2 = 0; kk2 < 64; kk2++) {
            float2 vv = *(const float2*)&vsh[kk2][2 * l];
            float a0 = ash[2 * qw][kk2];
            float a1 = ash[2 * qw + 1][kk2];
            acc[0][0] = fmaf(a0, vv.x, acc[0][0]);
            acc[0][1] = fmaf(a0, vv.y, acc[0][1]);
            acc[1][0] = fmaf(a1, vv.x, acc[1][0]);
            acc[1][1] = fmaf(a1, vv.y, acc[1][1]);
        }
    }
#pragma unroll
    for (int jq = 0; jq < 2; jq++) {
        int q = qt * 32 + 2 * qw + jq;
        float2 r;
        r.x = acc[jq][0]; r.y = acc[jq][1];
        *(float2*)&g_outh[((size_t)(n * 256 + q)) * 512 + h * 64 + 2 * l] = r;
    }
}

// ---- kE: out = outh @ Wout^T + bout; swizzled Ws ----
__global__ void kE(const float* __restrict__ Wout, const float* __restrict__ bout,
                   float* __restrict__ out) {
    __shared__ float Xs[16][64];
    __shared__ float Ws[64][64];   // (ml,j) -> [ml][((j>>2)^(ml&15))*4 + (j&3)]
    int rt = blockIdx.x, jt = blockIdx.y;
    int tid = threadIdx.x;
    int jid = tid & 15, rid = tid >> 4;
    ull acc2[2];
    acc2[0] = acc2[1] = 0ull;
    for (int mt = 0; mt < 8; mt++) {
        __syncthreads();
        {
            int r = tid >> 4, c4 = tid & 15;
            *(float4*)&Xs[r][c4 * 4] = *(const float4*)(g_outh +
                (size_t)(rt * 16 + r) * 512 + mt * 64 + c4 * 4);
        }
#pragma unroll
        for (int ii = 0; ii < 4; ii++) {
            int flat = ii * 256 + tid;           // float4 idx
            int j = flat >> 4, ml4 = flat & 15;
            float4 v = *(const float4*)(Wout +
                (size_t)(jt * 64 + j) * 512 + mt * 64 + ml4 * 4);
            float vv[4] = {v.x, v.y, v.z, v.w};
#pragma unroll
            for (int i = 0; i < 4; i++) {
                int ml = ml4 * 4 + i;
                Ws[ml][(((j >> 2) ^ (ml & 15)) << 2) + (j & 3)] = vv[i];
            }
        }
        __syncthreads();
#pragma unroll 8
        for (int ml = 0; ml < 64; ml++) {
            float u = Xs[rid][ml];
            ull u2 = pack2(u, u);
            ulonglong2 w2 = *(const ulonglong2*)&Ws[ml][(jid ^ (ml & 15)) << 2];
            acc2[0] = fma2(u2, w2.x, acc2[0]);
            acc2[1] = fma2(u2, w2.y, acc2[1]);
        }
    }
    int row = rt * 16 + rid;
    int col = jt * 64 + jid * 4;
    ull b01 = *(const ull*)(bout + col);
    ull b23 = *(const ull*)(bout + col + 2);
    ulonglong2 r;
    r.x = add2(acc2[0], b01);
    r.y = add2(acc2[1], b23);
    *(ulonglong2*)(out + (size_t)row * 512 + col) = r;
}

extern "C" void kernel_launch(void* const* d_in, const int* in_sizes, int n_in,
                              void* d_out, int out_size) {
    const float* values = (const float*)d_in[0];
    const float* keys   = (const float*)d_in[1];
    const float* query  = (const float*)d_in[2];
    const float* pos    = (const float*)d_in[3];
    const float* rel    = (const float*)d_in[4];
    const float* mask   = (const float*)d_in[5];
    const float* Wv   = (const float*)d_in[6];
    const float* Wk   = (const float*)d_in[7];
    const float* Wq   = (const float*)d_in[8];
    const float* Wpq  = (const float*)d_in[9];
    const float* Wpk  = (const float*)d_in[10];
    const float* Wrk  = (const float*)d_in[11];
    const float* Wrq  = (const float*)d_in[12];
    const float* Wout = (const float*)d_in[13];
    const float* bout = (const float*)d_in[14];
    float* out = (float*)d_out;

    static bool attr_done = false;
    if (!attr_done) {
        cudaFuncSetAttribute(kC, cudaFuncAttributeMaxDynamicSharedMemorySize, 82176);
        attr_done = true;
    }

    kA0<<<5, 256>>>(Wq, Wk, Wpq, Wpk, Wrk, Wrq, Wv);
    kA<<<128, 256>>>(values, keys, query, pos);
    kB<<<dim3(32, HH, NB), 256>>>(keys, pos, mask);
    kC<<<dim3(LL / 2, NB), 256, 82176>>>(rel);
    kD<<<dim3(8, HH, NB), 512>>>();
    kE<<<dim3(32, 8), 256>>>(Wout, bout, out);
}

// round 5
// speedup vs baseline: 1.3742x; 1.2561x over previous
#include <cuda_runtime.h>
#include <cstdint>

#define NB 2
#define LL 256
#define HH 8
#define DD 64
#define EE 512
#define INVS 0.70710678118654752440f

typedef unsigned long long ull;

__device__ __forceinline__ ull fma2(ull a, ull b, ull c) {
    ull d;
    asm("fma.rn.f32x2 %0, %1, %2, %3;" : "=l"(d) : "l"(a), "l"(b), "l"(c));
    return d;
}
__device__ __forceinline__ ull add2(ull a, ull b) {
    ull d;
    asm("add.rn.f32x2 %0, %1, %2;" : "=l"(d) : "l"(a), "l"(b));
    return d;
}
__device__ __forceinline__ ull pack2(float x, float y) {
    ull d;
    asm("mov.b64 %0, {%1, %2};" : "=l"(d) : "r"(__float_as_uint(x)), "r"(__float_as_uint(y)));
    return d;
}
__device__ __forceinline__ float lohi(ull s) {
    unsigned lo, hi;
    asm("mov.b64 {%0, %1}, %2;" : "=r"(lo), "=r"(hi) : "l"(s));
    return __uint_as_float(lo) + __uint_as_float(hi);
}
__device__ __forceinline__ void unpk(ull s, float& a, float& b) {
    unsigned lo, hi;
    asm("mov.b64 {%0, %1}, %2;" : "=r"(lo), "=r"(hi) : "l"(s));
    a = __uint_as_float(lo);
    b = __uint_as_float(hi);
}

// ---- scratch ----
__device__ float g_W[5 * 64 * 64];        // Mqk, Mp, Wa, Wb, WvT : [w][m][i]
__device__ float g_qm[NB * LL * EE];
__device__ float g_pm[NB * LL * EE];
__device__ float g_a [NB * LL * EE];
__device__ float g_b [NB * LL * EE];
__device__ float g_vp[NB * LL * EE];
__device__ float g_base[NB * HH * LL * LL];
__device__ float g_attn[NB * HH * LL * LL];
__device__ float g_outh[NB * LL * EE];

// ---- kA0: combined 64x64 weights ----
__global__ void kA0(const float* __restrict__ Wq, const float* __restrict__ Wk,
                    const float* __restrict__ Wpq, const float* __restrict__ Wpk,
                    const float* __restrict__ Wrk, const float* __restrict__ Wrq,
                    const float* __restrict__ Wv) {
    int w = blockIdx.x;
    int tid = threadIdx.x;
    __shared__ float Wr[4096];
    if (w == 4) {
        for (int o = tid; o < 4096; o += 256) {
            int m = o >> 6, i = o & 63;
            g_W[4 * 4096 + o] = Wv[i * 64 + m];
        }
        return;
    }
    const float *Wl, *Wrg;
    if (w == 0)      { Wl = Wq;  Wrg = Wk;  }
    else if (w == 1) { Wl = Wpq; Wrg = Wpk; }
    else if (w == 2) { Wl = Wq;  Wrg = Wrk; }
    else             { Wl = Wk;  Wrg = Wrq; }
    for (int o = tid; o < 4096; o += 256) Wr[o] = Wrg[o];
    __syncthreads();
    int m = tid & 63, jg = tid >> 6;
    float acc[16];
#pragma unroll
    for (int j = 0; j < 16; j++) acc[j] = 0.f;
    for (int t = 0; t < 64; t++) {
        float xl = Wl[t * 64 + m];
#pragma unroll
        for (int j = 0; j < 16; j++) acc[j] = fmaf(xl, Wr[t * 64 + jg * 16 + j], acc[j]);
    }
#pragma unroll
    for (int j = 0; j < 16; j++) g_W[w * 4096 + m * 64 + jg * 16 + j] = acc[j];
}

// ---- kA: 5 fused projections, 4 rows per block ----
__global__ void kA(const float* __restrict__ values, const float* __restrict__ keys,
                   const float* __restrict__ query, const float* __restrict__ pos) {
    __shared__ float xs[4][4][512];   // [tensor][row][col]
    int r0 = blockIdx.x * 4;
    int tid = threadIdx.x;
    const float* srcs[4] = {values, keys, query, pos};
#pragma unroll
    for (int ii = 0; ii < 8; ii++) {
        int flat = ii * 256 + tid;               // float4 index
        int ten = flat >> 9, row = (flat >> 7) & 3, c4 = flat & 127;
        *(float4*)&xs[ten][row][c4 * 4] =
            *(const float4*)(srcs[ten] + (size_t)(r0 + row) * 512 + c4 * 4);
    }
    __syncthreads();
    int i0 = 2 * tid;
    int hb = i0 & ~63, il = i0 & 63;
    const float* Mqk = g_W;
    const float* Mp  = g_W + 4096;
    const float* Wa  = g_W + 8192;
    const float* Wb  = g_W + 12288;
    const float* WvT = g_W + 16384;
    ull aqm[4], apm[4], aa[4], ab[4], av[4];
#pragma unroll
    for (int r = 0; r < 4; r++) { aqm[r]=0; apm[r]=0; aa[r]=0; ab[r]=0; av[r]=0; }
#pragma unroll 4
    for (int m = 0; m < 64; m++) {
        int wi = m * 64 + il;
        ull wqk = *(const ull*)&Mqk[wi];
        ull wp  = *(const ull*)&Mp [wi];
        ull wa  = *(const ull*)&Wa [wi];
        ull wb  = *(const ull*)&Wb [wi];
        ull wv  = *(const ull*)&WvT[wi];
#pragma unroll
        for (int r = 0; r < 4; r++) {
            float v_ = xs[0][r][hb + m], k_ = xs[1][r][hb + m];
            float q_ = xs[2][r][hb + m], p_ = xs[3][r][hb + m];
            aqm[r] = fma2(pack2(q_, q_), wqk, aqm[r]);
            apm[r] = fma2(pack2(p_, p_), wp,  apm[r]);
            aa [r] = fma2(pack2(q_, q_), wa,  aa [r]);
            ab [r] = fma2(pack2(k_, k_), wb,  ab [r]);
            av [r] = fma2(pack2(v_, v_), wv,  av [r]);
        }
    }
    ull s2 = pack2(INVS, INVS);
    ull z = 0;
#pragma unroll
    for (int r = 0; r < 4; r++) {
        size_t o = (size_t)(r0 + r) * 512 + i0;
        *(ull*)&g_qm[o] = fma2(aqm[r], s2, z);
        *(ull*)&g_pm[o] = fma2(apm[r], s2, z);
        *(ull*)&g_a [o] = fma2(aa [r], s2, z);
        *(ull*)&g_b [o] = fma2(ab [r], s2, z);
        *(ull*)&g_vp[o] = av[r];
    }
}

// ---- kB: base[n,h,q,k] = qm.keys + pm.pos + mask; swizzled Vsh ----
__global__ void kB(const float* __restrict__ keys, const float* __restrict__ pos,
                   const float* __restrict__ mask) {
    __shared__ float Ush[2][32][64];
    __shared__ float Vsh[2][64][64];   // (c,k) -> [c][((k>>2)^(c&15))*4 + (k&3)]
    int qt = blockIdx.x >> 2, kt = blockIdx.x & 3;
    int h = blockIdx.y, n = blockIdx.z;
    int tid = threadIdx.x;
    int kid = tid & 15, qid = tid >> 4;
#pragma unroll
    for (int ii = 0; ii < 4; ii++) {
        int flat = ii * 256 + tid;               // float4 idx
        int src = flat >> 9, q = (flat >> 4) & 31, c4 = flat & 15;
        *(float4*)&Ush[src][q][c4 * 4] =
            *(const float4*)((src ? g_pm : g_qm) +
                             (size_t)(n * 256 + qt * 32 + q) * 512 + h * 64 + c4 * 4);
    }
#pragma unroll
    for (int ii = 0; ii < 8; ii++) {
        int flat = ii * 256 + tid;               // float4 idx
        int src = flat >> 10, k = (flat >> 4) & 63, c4 = flat & 15;
        const float* V = src ? pos : keys;
        float4 v = *(const float4*)(V + (size_t)(n * 256 + kt * 64 + k) * 512 + h * 64 + c4 * 4);
        float vv[4] = {v.x, v.y, v.z, v.w};
#pragma unroll
        for (int i = 0; i < 4; i++) {
            int c = c4 * 4 + i;
            Vsh[src][c][(((k >> 2) ^ (c & 15)) << 2) + (k & 3)] = vv[i];
        }
    }
    __syncthreads();
    ull acc2[2][2];
    acc2[0][0] = acc2[0][1] = acc2[1][0] = acc2[1][1] = 0ull;
#pragma unroll
    for (int src = 0; src < 2; src++) {
#pragma unroll 4
        for (int c = 0; c < 64; c++) {
            float u0 = Ush[src][qid][c], u1 = Ush[src][qid + 16][c];
            ull u02 = pack2(u0, u0), u12 = pack2(u1, u1);
            ulonglong2 v2 = *(const ulonglong2*)&Vsh[src][c][(kid ^ (c & 15)) << 2];
            acc2[0][0] = fma2(u02, v2.x, acc2[0][0]);
            acc2[0][1] = fma2(u02, v2.y, acc2[0][1]);
            acc2[1][0] = fma2(u12, v2.x, acc2[1][0]);
            acc2[1][1] = fma2(u12, v2.y, acc2[1][1]);
        }
    }
    float4 m4 = *(const float4*)(mask + n * 256 + kt * 64 + kid * 4);
    float nm0 = (1.0f - m4.x) * -1e9f, nm1 = (1.0f - m4.y) * -1e9f;
    float nm2 = (1.0f - m4.z) * -1e9f, nm3 = (1.0f - m4.w) * -1e9f;
#pragma unroll
    for (int a = 0; a < 2; a++) {
        int q = qt * 32 + qid + 16 * a;
        float4 r;
        unpk(acc2[a][0], r.x, r.y);
        unpk(acc2[a][1], r.z, r.w);
        r.x += nm0; r.y += nm1; r.z += nm2; r.w += nm3;
        *(float4*)&g_base[((size_t)((n * 8 + h) * 256 + q)) * 256 + kt * 64 + kid * 4] = r;
    }
}

// ---- kC: barrier-free coalesced rel stream + exchange-network reduce + softmax ----
__global__ void __launch_bounds__(256, 2)
kC(const float* __restrict__ rel) {
    __shared__ float eng[2 * 8 * 260];
    const int n = blockIdx.y;
    const int q0 = blockIdx.x * 2;
    const int tid = threadIdx.x;
    const int w = tid >> 5, l = tid & 31;
    const bool b3 = (l & 8) != 0;
    const bool b2v = (l & 4) != 0;
    const int head = (l >> 4) + (b3 ? 4 : 0) + (b2v ? 2 : 0);

    // init eng from base (scaled + masked already)
#pragma unroll
    for (int ii = 0; ii < 4; ii++) {
        int flat = ii * 256 + tid;               // float4 idx over 4096
        int qi = flat >> 9, h = (flat >> 6) & 7, k4 = flat & 63;
        float4 v = *(const float4*)(g_base +
            ((size_t)((n * 8 + h) * 256 + q0 + qi)) * 256 + k4 * 4);
        float* e = &eng[(qi * 8 + h) * 260 + k4 * 4];
        e[0] = v.x; e[1] = v.y; e[2] = v.z; e[3] = v.w;
    }
    // a in regs: lane l, chunk u -> floats u*128 + l*4
    ulonglong2 areg[2][4];
#pragma unroll
    for (int q = 0; q < 2; q++)
#pragma unroll
        for (int u = 0; u < 4; u++)
            areg[q][u] = *(const ulonglong2*)(g_a +
                (size_t)(n * 256 + q0 + q) * 512 + u * 128 + l * 4);
    __syncthreads();

    const float* relb = rel + ((size_t)(n * 256 + q0)) * 256 * 512 + l * 4;
    const float* bbas = g_b + (size_t)n * 256 * 512 + l * 4;

    for (int t = 0; t < 32; t++) {
        const int k = t * 8 + w;
        const float* brow = bbas + (size_t)k * 512;
        const float* r0p  = relb + (size_t)k * 512;
        const float* r1p  = r0p + 256 * 512;
        ulonglong2 B[4], R0[4], R1[4];
#pragma unroll
        for (int u = 0; u < 4; u++) B[u]  = *(const ulonglong2*)(brow + u * 128);
#pragma unroll
        for (int u = 0; u < 4; u++) R0[u] = *(const ulonglong2*)(r0p + u * 128);
#pragma unroll
        for (int u = 0; u < 4; u++) R1[u] = *(const ulonglong2*)(r1p + u * 128);

        float s0[4], s1[4];
#pragma unroll
        for (int u = 0; u < 4; u++) {
            ull c0 = add2(areg[0][u].x, B[u].x);
            ull c1 = add2(areg[0][u].y, B[u].y);
            ull P  = fma2(R0[u].x, c0, 0ull);
            P      = fma2(R0[u].y, c1, P);
            s0[u] = lohi(P);
            ull d0 = add2(areg[1][u].x, B[u].x);
            ull d1 = add2(areg[1][u].y, B[u].y);
            ull Q  = fma2(R1[u].x, d0, 0ull);
            Q      = fma2(R1[u].y, d1, Q);
            s1[u] = lohi(Q);
        }
        // exchange-network reduction (16 lanes per head-half), both q at once
        float f, g;
        {
            float t0 = __shfl_xor_sync(0xffffffffu, s0[0], 8);
            float t1 = __shfl_xor_sync(0xffffffffu, s0[1], 8);
            float t2 = __shfl_xor_sync(0xffffffffu, s0[2], 8);
            float t3 = __shfl_xor_sync(0xffffffffu, s0[3], 8);
            float e0 = b3 ? (s0[2] + t2) : (s0[0] + t0);
            float e1 = b3 ? (s0[3] + t3) : (s0[1] + t1);
            float u0 = __shfl_xor_sync(0xffffffffu, e0, 4);
            float u1 = __shfl_xor_sync(0xffffffffu, e1, 4);
            f = b2v ? (e1 + u1) : (e0 + u0);
            f += __shfl_xor_sync(0xffffffffu, f, 1);
            f += __shfl_xor_sync(0xffffffffu, f, 2);
        }
        {
            float t0 = __shfl_xor_sync(0xffffffffu, s1[0], 8);
            float t1 = __shfl_xor_sync(0xffffffffu, s1[1], 8);
            float t2 = __shfl_xor_sync(0xffffffffu, s1[2], 8);
            float t3 = __shfl_xor_sync(0xffffffffu, s1[3], 8);
            float e0 = b3 ? (s1[2] + t2) : (s1[0] + t0);
            float e1 = b3 ? (s1[3] + t3) : (s1[1] + t1);
            float u0 = __shfl_xor_sync(0xffffffffu, e0, 4);
            float u1 = __shfl_xor_sync(0xffffffffu, e1, 4);
            g = b2v ? (e1 + u1) : (e0 + u0);
            g += __shfl_xor_sync(0xffffffffu, g, 1);
            g += __shfl_xor_sync(0xffffffffu, g, 2);
        }
        if ((l & 3) == 0) {
            eng[(0 * 8 + head) * 260 + k] += f;
            eng[(1 * 8 + head) * 260 + k] += g;
        }
    }
    __syncthreads();

    // softmax: warp w = head w, rows q0 and q0+1
#pragma unroll
    for (int qi = 0; qi < 2; qi++) {
        float v[8];
        float m = -1e30f;
#pragma unroll
        for (int j = 0; j < 8; j++) {
            v[j] = eng[(qi * 8 + w) * 260 + l + 32 * j];
            m = fmaxf(m, v[j]);
        }
#pragma unroll
        for (int off = 16; off; off >>= 1)
            m = fmaxf(m, __shfl_xor_sync(0xffffffffu, m, off));
        float s = 0.f;
#pragma unroll
        for (int j = 0; j < 8; j++) {
            v[j] = __expf(v[j] - m);
            s += v[j];
        }
#pragma unroll
        for (int off = 16; off; off >>= 1)
            s += __shfl_xor_sync(0xffffffffu, s, off);
        float inv = 1.0f / s;
#pragma unroll
        for (int j = 0; j < 8; j++)
            g_attn[((size_t)((n * 8 + w) * 256 + q0 + qi)) * 256 + l + 32 * j] = v[j] * inv;
    }
}

// ---- kD: outh[n,q,h,d] = sum_k attn[n,h,q,k] * vp[n,k,h,d] ----
__global__ void kD() {
    __shared__ float vsh[64][64];
    __shared__ float ash[32][64];
    int qt = blockIdx.x, h = blockIdx.y, n = blockIdx.z;
    int tid = threadIdx.x;
    int l = tid & 31, qw = tid >> 5;  // 16 warps -> 2 q each
    float acc[2][2];
    acc[0][0] = acc[0][1] = acc[1][0] = acc[1][1] = 0.f;
    for (int kp = 0; kp < 4; kp++) {
        __syncthreads();
#pragma unroll
        for (int ii = 0; ii < 2; ii++) {
            int flat = ii * 512 + tid;           // float4 idx
            int k = flat >> 4, d4 = flat & 15;
            *(float4*)&vsh[k][d4 * 4] = *(const float4*)(g_vp +
                ((size_t)(n * 256 + kp * 64 + k)) * 512 + h * 64 + d4 * 4);
        }
        {
            int q = tid >> 4, k4 = tid & 15;
            *(float4*)&ash[q][k4 * 4] = *(const float4*)(g_attn +
                ((size_t)((n * 8 + h) * 256 + qt * 32 + q)) * 256 + kp * 64 + k4 * 4);
        }
        __syncthreads();
#pragma unroll 4
        for (int kk2 = 0; kk2 < 64; kk2++) {
            float2 vv = *(const float2*)&vsh[kk2][2 * l];
            float a0 = ash[2 * qw][kk2];
            float a1 = ash[2 * qw + 1][kk2];
            acc[0][0] = fmaf(a0, vv.x, acc[0][0]);
            acc[0][1] = fmaf(a0, vv.y, acc[0][1]);
            acc[1][0] = fmaf(a1, vv.x, acc[1][0]);
            acc[1][1] = fmaf(a1, vv.y, acc[1][1]);
        }
    }
#pragma unroll
    for (int jq = 0; jq < 2; jq++) {
        int q = qt * 32 + 2 * qw + jq;
        float2 r;
        r.x = acc[jq][0]; r.y = acc[jq][1];
        *(float2*)&g_outh[((size_t)(n * 256 + q)) * 512 + h * 64 + 2 * l] = r;
    }
}

// ---- kE: out = outh @ Wout^T + bout; swizzled Ws ----
__global__ void kE(const float* __restrict__ Wout, const float* __restrict__ bout,
                   float* __restrict__ out) {
    __shared__ float Xs[16][64];
    __shared__ float Ws[64][64];   // (ml,j) -> [ml][((j>>2)^(ml&15))*4 + (j&3)]
    int rt = blockIdx.x, jt = blockIdx.y;
    int tid = threadIdx.x;
    int jid = tid & 15, rid = tid >> 4;
    ull acc2[2];
    acc2[0] = acc2[1] = 0ull;
    for (int mt = 0; mt < 8; mt++) {
        __syncthreads();
        {
            int r = tid >> 4, c4 = tid & 15;
            *(float4*)&Xs[r][c4 * 4] = *(const float4*)(g_outh +
                (size_t)(rt * 16 + r) * 512 + mt * 64 + c4 * 4);
        }
#pragma unroll
        for (int ii = 0; ii < 4; ii++) {
            int flat = ii * 256 + tid;           // float4 idx
            int j = flat >> 4, ml4 = flat & 15;
            float4 v = *(const float4*)(Wout +
                (size_t)(jt * 64 + j) * 512 + mt * 64 + ml4 * 4);
            float vv[4] = {v.x, v.y, v.z, v.w};
#pragma unroll
            for (int i = 0; i < 4; i++) {
                int ml = ml4 * 4 + i;
                Ws[ml][(((j >> 2) ^ (ml & 15)) << 2) + (j & 3)] = vv[i];
            }
        }
        __syncthreads();
#pragma unroll 8
        for (int ml = 0; ml < 64; ml++) {
            float u = Xs[rid][ml];
            ull u2 = pack2(u, u);
            ulonglong2 w2 = *(const ulonglong2*)&Ws[ml][(jid ^ (ml & 15)) << 2];
            acc2[0] = fma2(u2, w2.x, acc2[0]);
            acc2[1] = fma2(u2, w2.y, acc2[1]);
        }
    }
    int row = rt * 16 + rid;
    int col = jt * 64 + jid * 4;
    ull b01 = *(const ull*)(bout + col);
    ull b23 = *(const ull*)(bout + col + 2);
    ulonglong2 r;
    r.x = add2(acc2[0], b01);
    r.y = add2(acc2[1], b23);
    *(ulonglong2*)(out + (size_t)row * 512 + col) = r;
}

extern "C" void kernel_launch(void* const* d_in, const int* in_sizes, int n_in,
                              void* d_out, int out_size) {
    const float* values = (const float*)d_in[0];
    const float* keys   = (const float*)d_in[1];
    const float* query  = (const float*)d_in[2];
    const float* pos    = (const float*)d_in[3];
    const float* rel    = (const float*)d_in[4];
    const float* mask   = (const float*)d_in[5];
    const float* Wv   = (const float*)d_in[6];
    const float* Wk   = (const float*)d_in[7];
    const float* Wq   = (const float*)d_in[8];
    const float* Wpq  = (const float*)d_in[9];
    const float* Wpk  = (const float*)d_in[10];
    const float* Wrk  = (const float*)d_in[11];
    const float* Wrq  = (const float*)d_in[12];
    const float* Wout = (const float*)d_in[13];
    const float* bout = (const float*)d_in[14];
    float* out = (float*)d_out;

    kA0<<<5, 256>>>(Wq, Wk, Wpq, Wpk, Wrk, Wrq, Wv);
    kA<<<128, 256>>>(values, keys, query, pos);
    kB<<<dim3(32, HH, NB), 256>>>(keys, pos, mask);
    kC<<<dim3(LL / 2, NB), 256>>>(rel);
    kD<<<dim3(8, HH, NB), 512>>>();
    kE<<<dim3(32, 8), 256>>>(Wout, bout, out);
}

// round 6
// speedup vs baseline: 1.7573x; 1.2788x over previous
#include <cuda_runtime.h>
#include <cstdint>

#define NB 2
#define LL 256
#define HH 8
#define DD 64
#define EE 512
#define INVS 0.70710678118654752440f

typedef unsigned long long ull;

__device__ __forceinline__ ull fma2(ull a, ull b, ull c) {
    ull d;
    asm("fma.rn.f32x2 %0, %1, %2, %3;" : "=l"(d) : "l"(a), "l"(b), "l"(c));
    return d;
}
__device__ __forceinline__ ull add2(ull a, ull b) {
    ull d;
    asm("add.rn.f32x2 %0, %1, %2;" : "=l"(d) : "l"(a), "l"(b));
    return d;
}
__device__ __forceinline__ ull pack2(float x, float y) {
    ull d;
    asm("mov.b64 %0, {%1, %2};" : "=l"(d) : "r"(__float_as_uint(x)), "r"(__float_as_uint(y)));
    return d;
}
__device__ __forceinline__ float lohi(ull s) {
    unsigned lo, hi;
    asm("mov.b64 {%0, %1}, %2;" : "=r"(lo), "=r"(hi) : "l"(s));
    return __uint_as_float(lo) + __uint_as_float(hi);
}
__device__ __forceinline__ void unpk(ull s, float& a, float& b) {
    unsigned lo, hi;
    asm("mov.b64 {%0, %1}, %2;" : "=r"(lo), "=r"(hi) : "l"(s));
    a = __uint_as_float(lo);
    b = __uint_as_float(hi);
}

// ---- scratch ----
__device__ float g_qm[NB * LL * EE];   // q @ Wq^T * INVS
__device__ float g_k [NB * LL * EE];   // k @ Wk^T
__device__ float g_pq[NB * LL * EE];   // p @ Wpq^T * INVS
__device__ float g_pk[NB * LL * EE];   // p @ Wpk^T
__device__ float g_a [NB * LL * EE];   // qm @ Wrk            (INVS-scaled via qm)
__device__ float g_b [NB * LL * EE];   // (k' @ Wrq) * INVS
__device__ float g_vp[NB * LL * EE];   // v @ Wv^T
__device__ float g_base[NB * HH * LL * LL];
__device__ float g_outh[NB * LL * EE];

// ---- kA: per-head chained GEMMs. grid (rowtile 8, head 8, group 4) ----
// group 0: y1 = q@Wq^T *INVS -> g_qm ; y2 = y1@Wrk       -> g_a
// group 1: y1 = k@Wk^T       -> g_k  ; y2 = y1@Wrq *INVS -> g_b
// group 2: y1 = p@Wpq^T*INVS -> g_pq ; y2 = p@Wpk^T      -> g_pk
// group 3: y1 = v@Wv^T       -> g_vp
__global__ void __launch_bounds__(256)
kA(const float* __restrict__ query, const float* __restrict__ keys,
   const float* __restrict__ pos,   const float* __restrict__ values,
   const float* __restrict__ Wq,  const float* __restrict__ Wk,
   const float* __restrict__ Wpq, const float* __restrict__ Wpk,
   const float* __restrict__ Wrk, const float* __restrict__ Wrq,
   const float* __restrict__ Wv) {
    __shared__ float Xs[64][68];
    __shared__ float Ys[64][68];
    __shared__ float W1s[64][64];   // transposed+swizzled: (m,i)->[m][((i>>2)^(m&15))*4+(i&3)] = W1[i][m]
    __shared__ float W2s[64][64];   // z<2: plain row-major; z==2: transposed+swizzled
    const int rt = blockIdx.x, h = blockIdx.y, z = blockIdx.z;
    const int tid = threadIdx.x;
    const int cid = tid & 15, rid = tid >> 4;

    const float* src = (z == 0) ? query : (z == 1) ? keys : (z == 2) ? pos : values;
    const float* W1  = (z == 0) ? Wq    : (z == 1) ? Wk   : (z == 2) ? Wpq : Wv;
    const float* W2  = (z == 0) ? Wrk   : (z == 1) ? Wrq  : Wpk;

    // stage X tile (64 rows x head-cols 64)
#pragma unroll
    for (int ii = 0; ii < 4; ii++) {
        int flat = ii * 256 + tid;
        int r = flat >> 4, c4 = flat & 15;
        *(float4*)&Xs[r][c4 * 4] =
            *(const float4*)(src + (size_t)(rt * 64 + r) * 512 + h * 64 + c4 * 4);
    }
    // stage W1 transposed+swizzled
#pragma unroll
    for (int ii = 0; ii < 4; ii++) {
        int flat = ii * 256 + tid;
        int i = flat >> 4, m4 = flat & 15;
        float4 wv = *(const float4*)(W1 + (size_t)i * 64 + m4 * 4);
        float w4[4] = {wv.x, wv.y, wv.z, wv.w};
#pragma unroll
        for (int j = 0; j < 4; j++) {
            int m = m4 * 4 + j;
            W1s[m][(((i >> 2) ^ (m & 15)) << 2) + (i & 3)] = w4[j];
        }
    }
    // stage W2
    if (z < 2) {
#pragma unroll
        for (int ii = 0; ii < 4; ii++) {
            int flat = ii * 256 + tid;
            int i = flat >> 4, e4 = flat & 15;
            *(float4*)&W2s[i][e4 * 4] = *(const float4*)(W2 + (size_t)i * 64 + e4 * 4);
        }
    } else if (z == 2) {
#pragma unroll
        for (int ii = 0; ii < 4; ii++) {
            int flat = ii * 256 + tid;
            int i = flat >> 4, m4 = flat & 15;
            float4 wv = *(const float4*)(W2 + (size_t)i * 64 + m4 * 4);
            float w4[4] = {wv.x, wv.y, wv.z, wv.w};
#pragma unroll
            for (int j = 0; j < 4; j++) {
                int m = m4 * 4 + j;
                W2s[m][(((i >> 2) ^ (m & 15)) << 2) + (i & 3)] = w4[j];
            }
        }
    }
    __syncthreads();

    // GEMM1: y1[r][i] = sum_m Xs[r][m] * W1[i][m]
    ull acc[4][2];
#pragma unroll
    for (int rj = 0; rj < 4; rj++) { acc[rj][0] = 0; acc[rj][1] = 0; }
#pragma unroll 4
    for (int m = 0; m < 64; m++) {
        ulonglong2 wv = *(const ulonglong2*)&W1s[m][(cid ^ (m & 15)) << 2];
#pragma unroll
        for (int rj = 0; rj < 4; rj++) {
            float xa = Xs[rj * 16 + rid][m];
            ull xa2 = pack2(xa, xa);
            acc[rj][0] = fma2(xa2, wv.x, acc[rj][0]);
            acc[rj][1] = fma2(xa2, wv.y, acc[rj][1]);
        }
    }
    float s1 = (z == 0 || z == 2) ? INVS : 1.0f;
    float* out1 = (z == 0) ? g_qm : (z == 1) ? g_k : (z == 2) ? g_pq : g_vp;
    ull s1v = pack2(s1, s1);
#pragma unroll
    for (int rj = 0; rj < 4; rj++) {
        int row = rj * 16 + rid;
        ulonglong2 o;
        o.x = fma2(acc[rj][0], s1v, 0ull);
        o.y = fma2(acc[rj][1], s1v, 0ull);
        *(ulonglong2*)(out1 + (size_t)(rt * 64 + row) * 512 + h * 64 + cid * 4) = o;
        *(ulonglong2*)&Ys[row][cid * 4] = o;
    }
    if (z == 3) return;
    __syncthreads();

    // GEMM2
    ull acc2[4][2];
#pragma unroll
    for (int rj = 0; rj < 4; rj++) { acc2[rj][0] = 0; acc2[rj][1] = 0; }
    if (z < 2) {
        // y2[r][e] = sum_i Ys[r][i] * W2[i][e]
#pragma unroll 4
        for (int i = 0; i < 64; i++) {
            ulonglong2 wv = *(const ulonglong2*)&W2s[i][cid * 4];
#pragma unroll
            for (int rj = 0; rj < 4; rj++) {
                float ya = Ys[rj * 16 + rid][i];
                ull ya2 = pack2(ya, ya);
                acc2[rj][0] = fma2(ya2, wv.x, acc2[rj][0]);
                acc2[rj][1] = fma2(ya2, wv.y, acc2[rj][1]);
            }
        }
    } else {
        // y2[r][i] = sum_m Xs[r][m] * W2[i][m]
#pragma unroll 4
        for (int m = 0; m < 64; m++) {
            ulonglong2 wv = *(const ulonglong2*)&W2s[m][(cid ^ (m & 15)) << 2];
#pragma unroll
            for (int rj = 0; rj < 4; rj++) {
                float xa = Xs[rj * 16 + rid][m];
                ull xa2 = pack2(xa, xa);
                acc2[rj][0] = fma2(xa2, wv.x, acc2[rj][0]);
                acc2[rj][1] = fma2(xa2, wv.y, acc2[rj][1]);
            }
        }
    }
    float s2 = (z == 1) ? INVS : 1.0f;
    float* out2 = (z == 0) ? g_a : (z == 1) ? g_b : g_pk;
    ull s2v = pack2(s2, s2);
#pragma unroll
    for (int rj = 0; rj < 4; rj++) {
        int row = rj * 16 + rid;
        ulonglong2 o;
        o.x = fma2(acc2[rj][0], s2v, 0ull);
        o.y = fma2(acc2[rj][1], s2v, 0ull);
        *(ulonglong2*)(out2 + (size_t)(rt * 64 + row) * 512 + h * 64 + cid * 4) = o;
    }
}

// ---- kB: base[n,h,q,k] = qm.k' + pq.pk + mask; swizzled Vsh ----
__global__ void kB(const float* __restrict__ mask) {
    __shared__ float Ush[2][32][64];
    __shared__ float Vsh[2][64][64];   // (c,k) -> [c][((k>>2)^(c&15))*4 + (k&3)]
    int qt = blockIdx.x >> 2, kt = blockIdx.x & 3;
    int h = blockIdx.y, n = blockIdx.z;
    int tid = threadIdx.x;
    int kid = tid & 15, qid = tid >> 4;
#pragma unroll
    for (int ii = 0; ii < 4; ii++) {
        int flat = ii * 256 + tid;
        int src = flat >> 9, q = (flat >> 4) & 31, c4 = flat & 15;
        *(float4*)&Ush[src][q][c4 * 4] =
            *(const float4*)((src ? g_pq : g_qm) +
                             (size_t)(n * 256 + qt * 32 + q) * 512 + h * 64 + c4 * 4);
    }
#pragma unroll
    for (int ii = 0; ii < 8; ii++) {
        int flat = ii * 256 + tid;
        int src = flat >> 10, k = (flat >> 4) & 63, c4 = flat & 15;
        const float* V = src ? g_pk : g_k;
        float4 v = *(const float4*)(V + (size_t)(n * 256 + kt * 64 + k) * 512 + h * 64 + c4 * 4);
        float vv[4] = {v.x, v.y, v.z, v.w};
#pragma unroll
        for (int i = 0; i < 4; i++) {
            int c = c4 * 4 + i;
            Vsh[src][c][(((k >> 2) ^ (c & 15)) << 2) + (k & 3)] = vv[i];
        }
    }
    __syncthreads();
    ull acc2[2][2];
    acc2[0][0] = acc2[0][1] = acc2[1][0] = acc2[1][1] = 0ull;
#pragma unroll
    for (int src = 0; src < 2; src++) {
#pragma unroll 4
        for (int c = 0; c < 64; c++) {
            float u0 = Ush[src][qid][c], u1 = Ush[src][qid + 16][c];
            ull u02 = pack2(u0, u0), u12 = pack2(u1, u1);
            ulonglong2 v2 = *(const ulonglong2*)&Vsh[src][c][(kid ^ (c & 15)) << 2];
            acc2[0][0] = fma2(u02, v2.x, acc2[0][0]);
            acc2[0][1] = fma2(u02, v2.y, acc2[0][1]);
            acc2[1][0] = fma2(u12, v2.x, acc2[1][0]);
            acc2[1][1] = fma2(u12, v2.y, acc2[1][1]);
        }
    }
    float4 m4 = *(const float4*)(mask + n * 256 + kt * 64 + kid * 4);
    float nm0 = (1.0f - m4.x) * -1e9f, nm1 = (1.0f - m4.y) * -1e9f;
    float nm2 = (1.0f - m4.z) * -1e9f, nm3 = (1.0f - m4.w) * -1e9f;
#pragma unroll
    for (int a = 0; a < 2; a++) {
        int q = qt * 32 + qid + 16 * a;
        float4 r;
        unpk(acc2[a][0], r.x, r.y);
        unpk(acc2[a][1], r.z, r.w);
        r.x += nm0; r.y += nm1; r.z += nm2; r.w += nm3;
        *(float4*)&g_base[((size_t)((n * 8 + h) * 256 + q)) * 256 + kt * 64 + kid * 4] = r;
    }
}

// ---- kC: coalesced rel stream + exchange reduce + softmax + fused attn@v ----
__global__ void __launch_bounds__(256, 2)
kC(const float* __restrict__ rel) {
    __shared__ float eng[2 * 8 * 260];
    const int n = blockIdx.y;
    const int q0 = blockIdx.x * 2;
    const int tid = threadIdx.x;
    const int w = tid >> 5, l = tid & 31;
    const bool b3 = (l & 8) != 0;
    const bool b2v = (l & 4) != 0;
    const int head = (l >> 4) + (b3 ? 4 : 0) + (b2v ? 2 : 0);

    // init eng from base (scaled + masked already)
#pragma unroll
    for (int ii = 0; ii < 4; ii++) {
        int flat = ii * 256 + tid;
        int qi = flat >> 9, h = (flat >> 6) & 7, k4 = flat & 63;
        float4 v = *(const float4*)(g_base +
            ((size_t)((n * 8 + h) * 256 + q0 + qi)) * 256 + k4 * 4);
        float* e = &eng[(qi * 8 + h) * 260 + k4 * 4];
        e[0] = v.x; e[1] = v.y; e[2] = v.z; e[3] = v.w;
    }
    // a in regs: lane l, chunk u -> floats u*128 + l*4
    ulonglong2 areg[2][4];
#pragma unroll
    for (int q = 0; q < 2; q++)
#pragma unroll
        for (int u = 0; u < 4; u++)
            areg[q][u] = *(const ulonglong2*)(g_a +
                (size_t)(n * 256 + q0 + q) * 512 + u * 128 + l * 4);
    __syncthreads();

    const float* relb = rel + ((size_t)(n * 256 + q0)) * 256 * 512 + l * 4;
    const float* bbas = g_b + (size_t)n * 256 * 512 + l * 4;

    for (int t = 0; t < 32; t++) {
        const int k = t * 8 + w;
        const float* brow = bbas + (size_t)k * 512;
        const float* r0p  = relb + (size_t)k * 512;
        const float* r1p  = r0p + 256 * 512;
        ulonglong2 B[4], R0[4], R1[4];
#pragma unroll
        for (int u = 0; u < 4; u++) B[u]  = *(const ulonglong2*)(brow + u * 128);
#pragma unroll
        for (int u = 0; u < 4; u++) R0[u] = *(const ulonglong2*)(r0p + u * 128);
#pragma unroll
        for (int u = 0; u < 4; u++) R1[u] = *(const ulonglong2*)(r1p + u * 128);

        float s0[4], s1[4];
#pragma unroll
        for (int u = 0; u < 4; u++) {
            ull c0 = add2(areg[0][u].x, B[u].x);
            ull c1 = add2(areg[0][u].y, B[u].y);
            ull P  = fma2(R0[u].x, c0, 0ull);
            P      = fma2(R0[u].y, c1, P);
            s0[u] = lohi(P);
            ull d0 = add2(areg[1][u].x, B[u].x);
            ull d1 = add2(areg[1][u].y, B[u].y);
            ull Q  = fma2(R1[u].x, d0, 0ull);
            Q      = fma2(R1[u].y, d1, Q);
            s1[u] = lohi(Q);
        }
        float f, g;
        {
            float t0 = __shfl_xor_sync(0xffffffffu, s0[0], 8);
            float t1 = __shfl_xor_sync(0xffffffffu, s0[1], 8);
            float t2 = __shfl_xor_sync(0xffffffffu, s0[2], 8);
            float t3 = __shfl_xor_sync(0xffffffffu, s0[3], 8);
            float e0 = b3 ? (s0[2] + t2) : (s0[0] + t0);
            float e1 = b3 ? (s0[3] + t3) : (s0[1] + t1);
            float u0 = __shfl_xor_sync(0xffffffffu, e0, 4);
            float u1 = __shfl_xor_sync(0xffffffffu, e1, 4);
            f = b2v ? (e1 + u1) : (e0 + u0);
            f += __shfl_xor_sync(0xffffffffu, f, 1);
            f += __shfl_xor_sync(0xffffffffu, f, 2);
        }
        {
            float t0 = __shfl_xor_sync(0xffffffffu, s1[0], 8);
            float t1 = __shfl_xor_sync(0xffffffffu, s1[1], 8);
            float t2 = __shfl_xor_sync(0xffffffffu, s1[2], 8);
            float t3 = __shfl_xor_sync(0xffffffffu, s1[3], 8);
            float e0 = b3 ? (s1[2] + t2) : (s1[0] + t0);
            float e1 = b3 ? (s1[3] + t3) : (s1[1] + t1);
            float u0 = __shfl_xor_sync(0xffffffffu, e0, 4);
            float u1 = __shfl_xor_sync(0xffffffffu, e1, 4);
            g = b2v ? (e1 + u1) : (e0 + u0);
            g += __shfl_xor_sync(0xffffffffu, g, 1);
            g += __shfl_xor_sync(0xffffffffu, g, 2);
        }
        if ((l & 3) == 0) {
            eng[(0 * 8 + head) * 260 + k] += f;
            eng[(1 * 8 + head) * 260 + k] += g;
        }
    }
    __syncthreads();

    // softmax: warp w = head w, rows q0 and q0+1; probs back into eng
#pragma unroll
    for (int qi = 0; qi < 2; qi++) {
        float v[8];
        float m = -1e30f;
#pragma unroll
        for (int j = 0; j < 8; j++) {
            v[j] = eng[(qi * 8 + w) * 260 + l + 32 * j];
            m = fmaxf(m, v[j]);
        }
#pragma unroll
        for (int off = 16; off; off >>= 1)
            m = fmaxf(m, __shfl_xor_sync(0xffffffffu, m, off));
        float s = 0.f;
#pragma unroll
        for (int j = 0; j < 8; j++) {
            v[j] = __expf(v[j] - m);
            s += v[j];
        }
#pragma unroll
        for (int off = 16; off; off >>= 1)
            s += __shfl_xor_sync(0xffffffffu, s, off);
        float inv = 1.0f / s;
#pragma unroll
        for (int j = 0; j < 8; j++)
            eng[(qi * 8 + w) * 260 + l + 32 * j] = v[j] * inv;
    }
    __syncwarp();

    // fused attn @ vp : warp w = head w, lane -> d pair (2l, 2l+1)
    ull acc0 = 0, acc1 = 0;
    const float* vpb = g_vp + (size_t)n * 256 * 512 + w * 64 + 2 * l;
    const float* p0 = &eng[(0 * 8 + w) * 260];
    const float* p1 = &eng[(1 * 8 + w) * 260];
#pragma unroll 8
    for (int k = 0; k < 256; k++) {
        ull v2 = *(const ull*)(vpb + (size_t)k * 512);
        acc0 = fma2(pack2(p0[k], p0[k]), v2, acc0);
        acc1 = fma2(pack2(p1[k], p1[k]), v2, acc1);
    }
    *(ull*)(g_outh + ((size_t)(n * 256 + q0))     * 512 + w * 64 + 2 * l) = acc0;
    *(ull*)(g_outh + ((size_t)(n * 256 + q0 + 1)) * 512 + w * 64 + 2 * l) = acc1;
}

// ---- kE: out = outh @ Wout^T + bout; swizzled Ws ----
__global__ void kE(const float* __restrict__ Wout, const float* __restrict__ bout,
                   float* __restrict__ out) {
    __shared__ float Xs[16][64];
    __shared__ float Ws[64][64];   // (ml,j) -> [ml][((j>>2)^(ml&15))*4 + (j&3)]
    int rt = blockIdx.x, jt = blockIdx.y;
    int tid = threadIdx.x;
    int jid = tid & 15, rid = tid >> 4;
    ull acc2[2];
    acc2[0] = acc2[1] = 0ull;
    for (int mt = 0; mt < 8; mt++) {
        __syncthreads();
        {
            int r = tid >> 4, c4 = tid & 15;
            *(float4*)&Xs[r][c4 * 4] = *(const float4*)(g_outh +
                (size_t)(rt * 16 + r) * 512 + mt * 64 + c4 * 4);
        }
#pragma unroll
        for (int ii = 0; ii < 4; ii++) {
            int flat = ii * 256 + tid;
            int j = flat >> 4, ml4 = flat & 15;
            float4 v = *(const float4*)(Wout +
                (size_t)(jt * 64 + j) * 512 + mt * 64 + ml4 * 4);
            float vv[4] = {v.x, v.y, v.z, v.w};
#pragma unroll
            for (int i = 0; i < 4; i++) {
                int ml = ml4 * 4 + i;
                Ws[ml][(((j >> 2) ^ (ml & 15)) << 2) + (j & 3)] = vv[i];
            }
        }
        __syncthreads();
#pragma unroll 8
        for (int ml = 0; ml < 64; ml++) {
            float u = Xs[rid][ml];
            ull u2 = pack2(u, u);
            ulonglong2 w2 = *(const ulonglong2*)&Ws[ml][(jid ^ (ml & 15)) << 2];
            acc2[0] = fma2(u2, w2.x, acc2[0]);
            acc2[1] = fma2(u2, w2.y, acc2[1]);
        }
    }
    int row = rt * 16 + rid;
    int col = jt * 64 + jid * 4;
    ull b01 = *(const ull*)(bout + col);
    ull b23 = *(const ull*)(bout + col + 2);
    ulonglong2 r;
    r.x = add2(acc2[0], b01);
    r.y = add2(acc2[1], b23);
    *(ulonglong2*)(out + (size_t)row * 512 + col) = r;
}

extern "C" void kernel_launch(void* const* d_in, const int* in_sizes, int n_in,
                              void* d_out, int out_size) {
    const float* values = (const float*)d_in[0];
    const float* keys   = (const float*)d_in[1];
    const float* query  = (const float*)d_in[2];
    const float* pos    = (const float*)d_in[3];
    const float* rel    = (const float*)d_in[4];
    const float* mask   = (const float*)d_in[5];
    const float* Wv   = (const float*)d_in[6];
    const float* Wk   = (const float*)d_in[7];
    const float* Wq   = (const float*)d_in[8];
    const float* Wpq  = (const float*)d_in[9];
    const float* Wpk  = (const float*)d_in[10];
    const float* Wrk  = (const float*)d_in[11];
    const float* Wrq  = (const float*)d_in[12];
    const float* Wout = (const float*)d_in[13];
    const float* bout = (const float*)d_in[14];
    float* out = (float*)d_out;

    kA<<<dim3(8, 8, 4), 256>>>(query, keys, pos, values,
                               Wq, Wk, Wpq, Wpk, Wrk, Wrq, Wv);
    kB<<<dim3(32, HH, NB), 256>>>(mask);
    kC<<<dim3(LL / 2, NB), 256>>>(rel);
    kE<<<dim3(32, 8), 256>>>(Wout, bout, out);
}